// round 14
// baseline (speedup 1.0000x reference)
#include <cuda_runtime.h>
#include <cuda_bf16.h>
#include <cstdint>

typedef unsigned long long u64;
typedef unsigned int u32;
typedef unsigned char u8;
typedef signed char s8;

// Shapes (fixed by the problem)
#define BB    8
#define CC    512
#define NN    1024
#define HH    8
#define DD    64
#define CQKV  1536

// LIF time-chunking
#define LCH   128
#define LWM   64

// ---------------------------------------------------------------------------
// Device scratch
// ---------------------------------------------------------------------------
__device__ s8  g_xq[BB * NN * CC];                   // pre-LIF spikes s8, [b][n][c]
__device__ float g_z [BB * CQKV * NN];               // Wqkv @ xq, [b][o][n]
__device__ __nv_bfloat16 g_sqh[BB * CC * NN];        // q spikes bf16, [b][c][n]
__device__ u64 g_kb[BB * CC * 16];                   // k spikes bitpacked along n
__device__ u64 g_vb[BB * CC * 16];                   // v spikes bitpacked along n
__device__ float g_y [BB * CC * NN];                 // attention out * 0.25
__device__ s8  g_sy[BB * NN * CC];                   // attn LIF spikes s8, [b][n][c]
__device__ s8  g_dA[4 * CQKV * CC];                  // qkv weight digits [4][1536][512]
__device__ s8  g_dP[4 * CC * CC];                    // proj weight digits [4][512][512]
__device__ float g_sA[CQKV];                         // per-row scales (pow2)
__device__ float g_sP[CC];

// ---------------------------------------------------------------------------
// PTX helpers
// ---------------------------------------------------------------------------
__device__ __forceinline__ void cpa16(u32 dst, const void* src) {
    asm volatile("cp.async.cg.shared.global [%0], [%1], 16;\n" :: "r"(dst), "l"(src));
}
__device__ __forceinline__ void cpa_commit() {
    asm volatile("cp.async.commit_group;\n");
}
__device__ __forceinline__ void ldsm4(u32* r, u32 addr) {
    asm volatile("ldmatrix.sync.aligned.m8n8.x4.shared.b16 {%0,%1,%2,%3}, [%4];"
        : "=r"(r[0]), "=r"(r[1]), "=r"(r[2]), "=r"(r[3]) : "r"(addr));
}
__device__ __forceinline__ void mma_s8(int* d, const u32* a, u32 b0, u32 b1) {
    asm volatile(
        "mma.sync.aligned.m16n8k32.row.col.s32.s8.s8.s32 "
        "{%0,%1,%2,%3}, {%4,%5,%6,%7}, {%8,%9}, {%0,%1,%2,%3};"
        : "+r"(d[0]), "+r"(d[1]), "+r"(d[2]), "+r"(d[3])
        : "r"(a[0]), "r"(a[1]), "r"(a[2]), "r"(a[3]), "r"(b0), "r"(b1));
}

// ---------------------------------------------------------------------------
// Prep: 4-digit base-128 fixed-point split of weights, per-row pow2 scale.
// w = s * (((d1*128 + d2)*128 + d3)*128 + d4) + r,  |r| <= s/2, s = 2^(e-25).
// One warp per output row. 2048 rows total (1536 qkv + 512 proj).
// ---------------------------------------------------------------------------
__global__ __launch_bounds__(128) void split8_kernel(
    const float* __restrict__ wq, const float* __restrict__ wk,
    const float* __restrict__ wv, const float* __restrict__ wp)
{
    const int w    = threadIdx.x >> 5;
    const int lane = threadIdx.x & 31;
    const int rid  = blockIdx.x * 4 + w;             // 0..2047

    const float* src;
    s8* dst; float* scp; int mrow, Mtot;
    if (rid < 1536) {
        src = (rid < 512) ? wq : (rid < 1024) ? wk : wv;
        src += (size_t)(rid & 511) * 512;
        dst = g_dA; scp = g_sA; mrow = rid; Mtot = CQKV;
    } else {
        src = wp + (size_t)(rid - 1536) * 512;
        dst = g_dP; scp = g_sP; mrow = rid - 1536; Mtot = CC;
    }

    float wv16[16];
    #pragma unroll
    for (int i = 0; i < 4; i++)
        *(float4*)&wv16[i * 4] = *(const float4*)(src + lane * 16 + i * 4);

    float mx = 0.0f;
    #pragma unroll
    for (int i = 0; i < 16; i++) mx = fmaxf(mx, fabsf(wv16[i]));
    #pragma unroll
    for (int off = 16; off > 0; off >>= 1)
        mx = fmaxf(mx, __shfl_xor_sync(0xFFFFFFFF, mx, off));
    mx = fmaxf(mx, 1e-30f);

    int e = ilogbf(mx);
    float s  = exp2f((float)(e - 25));
    float is = exp2f((float)(25 - e));
    if (lane == 0) scp[mrow] = s;

    u32 pk[4][4];
    #pragma unroll
    for (int p = 0; p < 4; p++)
        #pragma unroll
        for (int g = 0; g < 4; g++) pk[p][g] = 0;

    #pragma unroll
    for (int i = 0; i < 16; i++) {
        float a  = wv16[i] * is;                     // exact (pow2 scale)
        float d1 = rintf(a * 0x1p-21f);
        float r  = fmaf(d1, -0x1p21f, a);
        float d2 = rintf(r * 0x1p-14f);
        r = fmaf(d2, -0x1p14f, r);
        float d3 = rintf(r * 0x1p-7f);
        r = fmaf(d3, -0x1p7f, r);
        float d4 = rintf(r);
        int sh = (i & 3) * 8;
        pk[0][i >> 2] |= ((u32)((int)d1 & 0xFF)) << sh;
        pk[1][i >> 2] |= ((u32)((int)d2 & 0xFF)) << sh;
        pk[2][i >> 2] |= ((u32)((int)d3 & 0xFF)) << sh;
        pk[3][i >> 2] |= ((u32)((int)d4 & 0xFF)) << sh;
    }
    #pragma unroll
    for (int p = 0; p < 4; p++)
        *(uint4*)(dst + ((size_t)p * Mtot + mrow) * 512 + lane * 16) =
            make_uint4(pk[p][0], pk[p][1], pk[p][2], pk[p][3]);
}

// ---------------------------------------------------------------------------
// INT8 tensor-core GEMM with chained digit accumulation.
// C[b][M][1024] = scale_row * sum_digits( D_p[M][512] @ spikes[b][n][c]^T )
// Block tile 128x128; B (spikes, s8) resident in smem (128n x 512k, pad 528);
// A digit-planes streamed, BK=64, 3-slot ring; acc s32, <<7 between passes.
// Epilogue: exact hi/lo fp32 reconstruction (+ bias/BN for proj).
// ---------------------------------------------------------------------------
#define AOFF  67584              // B resident: 128 * 528
#define ASTG8 10240              // 128 rows * 80B
#define GS8   (AOFF + 3 * ASTG8) // 98304

template<bool EPI>
__global__ __launch_bounds__(256, 2) void gemm_s8_kernel(
    const s8* __restrict__ Wd,       // [4][M][512] digit planes
    const float* __restrict__ sc,    // [M] pow2 scales
    const s8* __restrict__ Bsp,      // [BB][1024][512] spikes
    float* __restrict__ C, int M,
    const float* __restrict__ bias, const float* __restrict__ bnp)
{
    extern __shared__ __align__(16) char smem[];
    const u32 sb = (u32)__cvta_generic_to_shared(smem);

    const int b  = blockIdx.z;
    const int mt = blockIdx.y;
    const int nt = blockIdx.x;
    const int tid  = threadIdx.x;
    const int lane = tid & 31;
    const int warp = tid >> 5;
    const int wm = warp & 3;
    const int wn = warp >> 2;

    const s8* Bg = Bsp + (size_t)b * (NN * CC) + (size_t)nt * 128 * CC;

    int acc[2][8][4];
    #pragma unroll
    for (int i = 0; i < 2; i++)
        #pragma unroll
        for (int j = 0; j < 8; j++)
            #pragma unroll
            for (int r = 0; r < 4; r++) acc[i][j][r] = 0;

    // B resident: 4096 x 16B chunks
    #pragma unroll
    for (int j = 0; j < 16; j++) {
        int idx = j * 256 + tid;
        int n = idx >> 5, ch = idx & 31;
        cpa16(sb + n * 528 + ch * 16, Bg + (size_t)n * 512 + ch * 16);
    }
    cpa_commit();

    auto loadA = [&](int slot, int pass, int k0) {
        #pragma unroll
        for (int j = 0; j < 2; j++) {
            int idx = tid * 2 + j;
            int row = idx >> 2, ch = idx & 3;
            cpa16(sb + AOFF + slot * ASTG8 + row * 80 + ch * 16,
                  Wd + ((size_t)(pass * M + mt * 128 + row)) * 512 + k0 + ch * 16);
        }
        cpa_commit();
    };

    loadA(0, 0, 0);
    loadA(1, 0, 64);

    for (int gs = 0; gs < 32; gs++) {
        asm volatile("cp.async.wait_group 1;\n");
        __syncthreads();

        if (gs && (gs & 7) == 0) {
            #pragma unroll
            for (int i = 0; i < 2; i++)
                #pragma unroll
                for (int j = 0; j < 8; j++)
                    #pragma unroll
                    for (int r = 0; r < 4; r++) acc[i][j][r] <<= 7;
        }

        const u32 aB = sb + AOFF + (gs % 3) * ASTG8;

        #pragma unroll
        for (int ks = 0; ks < 2; ks++) {
            u32 bq[4][4];
            #pragma unroll
            for (int nb = 0; nb < 4; nb++) {
                int row = wn * 64 + nb * 16 + ((lane >> 4) << 3) + (lane & 7);
                int kb  = ks * 32 + ((lane >> 3) & 1) * 16;
                ldsm4(bq[nb], sb + row * 528 + kb);
            }
            #pragma unroll
            for (int mi = 0; mi < 2; mi++) {
                u32 aq[4];
                ldsm4(aq, aB + (wm * 32 + mi * 16 + (lane & 15)) * 80
                          + ks * 32 + ((lane >> 4) << 4));
                #pragma unroll
                for (int j = 0; j < 8; j++)
                    mma_s8(acc[mi][j], aq,
                           bq[j >> 1][(j & 1) * 2], bq[j >> 1][(j & 1) * 2 + 1]);
            }
        }

        if (gs + 2 < 32) loadA((gs + 2) % 3, (gs + 2) >> 3, ((gs + 2) & 7) * 64);
        else             cpa_commit();
    }

    // Epilogue: z = s*acc exactly via hi/lo split, single fp32 rounding.
    #pragma unroll
    for (int mi = 0; mi < 2; mi++) {
        #pragma unroll
        for (int r2 = 0; r2 < 2; r2++) {
            int grow = mt * 128 + wm * 32 + mi * 16 + (lane >> 2) + r2 * 8;
            float s   = sc[grow];
            float s16 = s * 65536.0f;
            float inv = 1.0f, mu = 0.0f, be = 0.0f, bi = 0.0f;
            if (EPI) {
                float g  = bnp[grow];
                be = bnp[512 + grow];
                mu = bnp[1024 + grow];
                float va = bnp[1536 + grow];
                inv = g * rsqrtf(va + 1e-5f);
                bi = bias[grow];
            }
            float* crow = C + (size_t)b * M * NN + (size_t)grow * NN
                          + nt * 128 + wn * 64 + (lane & 3) * 2;
            #pragma unroll
            for (int j = 0; j < 8; j++) {
                int a0 = acc[mi][j][r2 * 2];
                int a1 = acc[mi][j][r2 * 2 + 1];
                float z0 = fmaf((float)(a0 >> 16), s16, (float)(a0 & 0xFFFF) * s);
                float z1 = fmaf((float)(a1 >> 16), s16, (float)(a1 & 0xFFFF) * s);
                if (EPI) {
                    z0 = (z0 + bi - mu) * inv + be;
                    z1 = (z1 + bi - mu) * inv + be;
                }
                *(float2*)(crow + j * 8) = make_float2(z0, z1);
            }
        }
    }
}

// ---------------------------------------------------------------------------
// LIF (K1/K5), time-chunked, s8 spike output TRANSPOSED [b][n][c].
// ---------------------------------------------------------------------------
__global__ __launch_bounds__(32) void lif3s_kernel(
    const float* __restrict__ in, const float* __restrict__ bnp,
    s8* __restrict__ out, float vth)
{
    __shared__ float buf[32][33];
    __shared__ __align__(16) u8 sb8[32][48];
    const int lane = threadIdx.x;
    const int r0   = blockIdx.x * 32;
    const int row  = r0 + lane;
    const int ch   = blockIdx.y;
    const int bidx = r0 >> 9;
    const int c0   = r0 & 511;

    float inv = 1.0f, mu = 0.0f, be = 0.0f;
    if (bnp) {
        int c = row & (CC - 1);
        inv = bnp[c] * (1.0f / sqrtf(bnp[3 * CC + c] + 1e-5f));
        be  = bnp[CC + c];
        mu  = bnp[2 * CC + c];
    }

    const int wt     = (ch == 0) ? 0 : (LWM / 32);
    const int ntiles = (LCH / 32) + wt;
    const int start  = ch * LCH - wt * 32;

    const float* src = in + (size_t)r0 * NN;

    float4 nxt[8];
    #pragma unroll
    for (int i = 0; i < 8; i++) {
        int f = lane + 32 * i;
        nxt[i] = *(const float4*)(src + (size_t)(f >> 3) * NN + start + (f & 7) * 4);
    }

    float v = 0.0f;
    for (int t = 0; t < ntiles; t++) {
        #pragma unroll
        for (int i = 0; i < 8; i++) {
            int f = lane + 32 * i;
            int r = f >> 3, cc = (f & 7) * 4;
            buf[r][cc + 0] = nxt[i].x;
            buf[r][cc + 1] = nxt[i].y;
            buf[r][cc + 2] = nxt[i].z;
            buf[r][cc + 3] = nxt[i].w;
        }
        __syncwarp();
        if (t + 1 < ntiles) {
            #pragma unroll
            for (int i = 0; i < 8; i++) {
                int f = lane + 32 * i;
                nxt[i] = *(const float4*)(src + (size_t)(f >> 3) * NN
                                          + start + (t + 1) * 32 + (f & 7) * 4);
            }
        }
        #pragma unroll
        for (int kk = 0; kk < 32; kk++) {
            float x  = buf[lane][kk];
            float xb = (x - mu) * inv + be;
            v = v + (xb - v) * 0.5f;
            bool sp = (v >= vth);
            v = sp ? 0.0f : v;
            sb8[kk][lane] = sp ? (u8)1 : (u8)0;
        }
        __syncwarp();
        if (t >= wt) {
            int n = start + t * 32 + lane;
            s8* dr = out + ((size_t)bidx * NN + n) * CC + c0;
            *(uint4*)(dr)      = *(const uint4*)&sb8[lane][0];
            *(uint4*)(dr + 16) = *(const uint4*)&sb8[lane][16];
        }
        __syncwarp();
    }
}

// ---------------------------------------------------------------------------
// LIF (K3): time-chunked BN+LIF on QKV output; q -> bf16 [c][n], k/v bitpacked.
// ---------------------------------------------------------------------------
__global__ __launch_bounds__(32) void lif_qkv3_kernel(
    const float* __restrict__ bnq, const float* __restrict__ bnk,
    const float* __restrict__ bnv)
{
    __shared__ float buf[32][33];
    const int lane = threadIdx.x;
    const int r0g  = blockIdx.x * 32;
    const int ch   = blockIdx.y;
    const int b    = r0g / CQKV;
    const int o    = r0g % CQKV;
    const int br   = o >> 9;
    const int c    = (o & 511) + lane;

    const float* bnp = (br == 0) ? bnq : (br == 1) ? bnk : bnv;
    float inv = bnp[c] * (1.0f / sqrtf(bnp[3 * CC + c] + 1e-5f));
    float be  = bnp[CC + c];
    float mu  = bnp[2 * CC + c];

    const int wt     = (ch == 0) ? 0 : (LWM / 32);
    const int ntiles = (LCH / 32) + wt;
    const int start  = ch * LCH - wt * 32;

    const float* src = g_z + (size_t)r0g * NN;
    __nv_bfloat16* qdst = g_sqh + ((size_t)b * CC + c) * NN;
    u64* bdst = ((br == 1) ? g_kb : g_vb) + ((size_t)b * CC + c) * 16;

    float4 nxt[8];
    #pragma unroll
    for (int i = 0; i < 8; i++) {
        int f = lane + 32 * i;
        nxt[i] = *(const float4*)(src + (size_t)(f >> 3) * NN + start + (f & 7) * 4);
    }

    float v = 0.0f;
    u32 prevbits = 0;
    for (int t = 0; t < ntiles; t++) {
        #pragma unroll
        for (int i = 0; i < 8; i++) {
            int f = lane + 32 * i;
            int r = f >> 3, cc = (f & 7) * 4;
            buf[r][cc + 0] = nxt[i].x;
            buf[r][cc + 1] = nxt[i].y;
            buf[r][cc + 2] = nxt[i].z;
            buf[r][cc + 3] = nxt[i].w;
        }
        __syncwarp();
        if (t + 1 < ntiles) {
            #pragma unroll
            for (int i = 0; i < 8; i++) {
                int f = lane + 32 * i;
                nxt[i] = *(const float4*)(src + (size_t)(f >> 3) * NN
                                          + start + (t + 1) * 32 + (f & 7) * 4);
            }
        }
        u32 pk[16];
        u32 tb = 0;
        #pragma unroll
        for (int kk = 0; kk < 32; kk++) {
            float x  = buf[lane][kk];
            float xb = (x - mu) * inv + be;
            v = v + (xb - v) * 0.5f;
            bool sp = (v >= 1.0f);
            v = sp ? 0.0f : v;
            if (br == 0) {
                u32 sbv = sp ? 0x3F80u : 0u;
                if (kk & 1) pk[kk >> 1] |= sbv << 16;
                else        pk[kk >> 1]  = sbv;
            } else {
                tb |= (sp ? 1u : 0u) << kk;
            }
        }
        __syncwarp();
        if (t >= wt) {
            int et  = t - wt;
            int col = ch * LCH + et * 32;
            if (br == 0) {
                #pragma unroll
                for (int j = 0; j < 4; j++) {
                    uint4 q = make_uint4(pk[j*4], pk[j*4+1], pk[j*4+2], pk[j*4+3]);
                    *(uint4*)(qdst + col + j * 8) = q;
                }
            } else {
                if (et & 1) bdst[ch * 2 + (et >> 1)] = ((u64)tb << 32) | (u64)prevbits;
                else        prevbits = tb;
            }
        }
    }
}

// ---------------------------------------------------------------------------
// attn: y = q @ (k^T v) * 0.25 per (b,h); d-split x2, n-split x8.
// ---------------------------------------------------------------------------
__global__ __launch_bounds__(128) void attn3_kernel()
{
    __shared__ u64 kbs[64][16];
    __shared__ u64 vbs[32][16];
    __shared__ __align__(16) float Gs[64][32];

    const int nc = blockIdx.x;
    const int h  = blockIdx.y >> 1;
    const int dh = blockIdx.y & 1;
    const int b  = blockIdx.z;
    const int tid = threadIdx.x;
    const size_t base_c = (size_t)b * CC + h * DD;

    for (int i = tid; i < 64 * 16; i += 128) {
        int d = i >> 4, j = i & 15;
        kbs[d][j] = g_kb[(base_c + d) * 16 + j];
    }
    for (int i = tid; i < 32 * 16; i += 128) {
        int d = i >> 4, j = i & 15;
        vbs[d][j] = g_vb[(base_c + dh * 32 + d) * 16 + j];
    }
    __syncthreads();

    for (int e = tid; e < 64 * 32; e += 128) {
        int dp = e >> 5, dd = e & 31;
        int gsum = 0;
        #pragma unroll
        for (int j = 0; j < 16; j++)
            gsum += __popcll(kbs[dp][j] & vbs[dd][j]);
        Gs[dp][dd] = (float)gsum;
    }
    __syncthreads();

    const int n = nc * 128 + tid;
    const __nv_bfloat16* qb = g_sqh + base_c * NN + n;

    float acc[32];
    #pragma unroll
    for (int d = 0; d < 32; d++) acc[d] = 0.0f;

    #pragma unroll 4
    for (int dp = 0; dp < 64; dp++) {
        float qv = __bfloat162float(qb[(size_t)dp * NN]);
        const float4* gr = (const float4*)&Gs[dp][0];
        #pragma unroll
        for (int j = 0; j < 8; j++) {
            float4 g4 = gr[j];
            acc[j * 4 + 0] += qv * g4.x;
            acc[j * 4 + 1] += qv * g4.y;
            acc[j * 4 + 2] += qv * g4.z;
            acc[j * 4 + 3] += qv * g4.w;
        }
    }
    #pragma unroll
    for (int d = 0; d < 32; d++)
        g_y[(base_c + dh * 32 + d) * NN + n] = acc[d] * 0.25f;
}

// ---------------------------------------------------------------------------
// Launch
// ---------------------------------------------------------------------------
extern "C" void kernel_launch(void* const* d_in, const int* in_sizes, int n_in,
                              void* d_out, int out_size)
{
    const float* x       = (const float*)d_in[0];
    const float* bn_pre  = (const float*)d_in[1];
    const float* w_q     = (const float*)d_in[2];
    const float* bn_q    = (const float*)d_in[3];
    const float* w_k     = (const float*)d_in[4];
    const float* bn_k    = (const float*)d_in[5];
    const float* w_v     = (const float*)d_in[6];
    const float* bn_v    = (const float*)d_in[7];
    const float* w_proj  = (const float*)d_in[8];
    const float* b_proj  = (const float*)d_in[9];
    const float* bn_proj = (const float*)d_in[10];
    float* out = (float*)d_out;

    s8* xq_ptr; cudaGetSymbolAddress((void**)&xq_ptr, g_xq);
    s8* sy_ptr; cudaGetSymbolAddress((void**)&sy_ptr, g_sy);
    s8* dA_ptr; cudaGetSymbolAddress((void**)&dA_ptr, g_dA);
    s8* dP_ptr; cudaGetSymbolAddress((void**)&dP_ptr, g_dP);
    float* sA_ptr; cudaGetSymbolAddress((void**)&sA_ptr, g_sA);
    float* sP_ptr; cudaGetSymbolAddress((void**)&sP_ptr, g_sP);
    float* z_ptr;  cudaGetSymbolAddress((void**)&z_ptr, g_z);
    float* y_ptr;  cudaGetSymbolAddress((void**)&y_ptr, g_y);

    cudaFuncSetAttribute(gemm_s8_kernel<false>,
                         cudaFuncAttributeMaxDynamicSharedMemorySize, GS8);
    cudaFuncSetAttribute(gemm_s8_kernel<true>,
                         cudaFuncAttributeMaxDynamicSharedMemorySize, GS8);

    // P0: 4-digit int8 weight split, per-row pow2 scale
    split8_kernel<<<512, 128>>>(w_q, w_k, w_v, w_proj);

    // K1: pre BN + LIF -> xq spikes (s8, [b][n][c])
    lif3s_kernel<<<dim3((BB * CC) / 32, NN / LCH), 32>>>(x, bn_pre, xq_ptr, 1.0f);

    // K2: fused QKV GEMM (int8 tensor cores, exact digit accumulation)
    gemm_s8_kernel<false><<<dim3(8, 12, 8), 256, GS8>>>(
        dA_ptr, sA_ptr, xq_ptr, z_ptr, CQKV, nullptr, nullptr);

    // K3: per-branch BN + LIF; q -> bf16 [c][n], k/v -> bitpacked
    lif_qkv3_kernel<<<dim3((BB * CQKV) / 32, NN / LCH), 32>>>(bn_q, bn_k, bn_v);

    // K4: linear attention via G = k^T v (popcount), y = q G * 0.25
    attn3_kernel<<<dim3(8, 16, 8), 128>>>();

    // K5: attn LIF (threshold 0.5) -> sy spikes (s8, [b][n][c])
    lif3s_kernel<<<dim3((BB * CC) / 32, NN / LCH), 32>>>(y_ptr, nullptr, sy_ptr, 0.5f);

    // K6: projection GEMM + bias + bn_proj fused epilogue -> out
    gemm_s8_kernel<true><<<dim3(8, 4, 8), 256, GS8>>>(
        dP_ptr, sP_ptr, sy_ptr, out, CC, b_proj, bn_proj);
}

// round 15
// speedup vs baseline: 2.7734x; 2.7734x over previous
#include <cuda_runtime.h>
#include <cuda_bf16.h>
#include <cstdint>

typedef unsigned long long u64;
typedef unsigned int u32;

// Shapes (fixed by the problem)
#define BB    8
#define CC    512
#define NN    1024
#define HH    8
#define DD    64
#define CQKV  1536

// LIF time-chunking: 8 chunks of 128 steps, 64-step warmup
#define LCH   128
#define LWM   64

// ---------------------------------------------------------------------------
// Device scratch
// ---------------------------------------------------------------------------
__device__ __nv_bfloat16 g_xq[BB * CC * NN];         // pre-LIF spikes (bf16), [b][c][n]
__device__ float g_z [BB * CQKV * NN];               // Wqkv @ xq, [b][o][n]
__device__ __nv_bfloat16 g_sqh[BB * CC * NN];        // q spikes bf16, [b][c][n]
__device__ u64 g_kb[BB * CC * 16];                   // k spikes bitpacked along n
__device__ u64 g_vb[BB * CC * 16];                   // v spikes bitpacked along n
__device__ float g_y [BB * CC * NN];                 // attention out * 0.25
__device__ __nv_bfloat16 g_sy[BB * CC * NN];         // attn LIF spikes, [b][c][n]
__device__ __nv_bfloat16 g_wA[3 * CQKV * CC];        // [3][1536][512] qkv splits
__device__ __nv_bfloat16 g_wP[3 * CC * CC];          // [3][512][512]  proj splits

// ---------------------------------------------------------------------------
// PTX helpers
// ---------------------------------------------------------------------------
__device__ __forceinline__ void cpa16(u32 dst, const void* src) {
    asm volatile("cp.async.cg.shared.global [%0], [%1], 16;\n" :: "r"(dst), "l"(src));
}
__device__ __forceinline__ void cpa_commit() {
    asm volatile("cp.async.commit_group;\n");
}
__device__ __forceinline__ void ldsm4(u32* r, u32 addr) {
    asm volatile("ldmatrix.sync.aligned.m8n8.x4.shared.b16 {%0,%1,%2,%3}, [%4];"
        : "=r"(r[0]), "=r"(r[1]), "=r"(r[2]), "=r"(r[3]) : "r"(addr));
}
__device__ __forceinline__ void ldsm4t(u32* r, u32 addr) {
    asm volatile("ldmatrix.sync.aligned.m8n8.x4.trans.shared.b16 {%0,%1,%2,%3}, [%4];"
        : "=r"(r[0]), "=r"(r[1]), "=r"(r[2]), "=r"(r[3]) : "r"(addr));
}
__device__ __forceinline__ void mma_bf16(float* d, const u32* a, u32 b0, u32 b1) {
    asm volatile(
        "mma.sync.aligned.m16n8k16.row.col.f32.bf16.bf16.f32 "
        "{%0,%1,%2,%3}, {%4,%5,%6,%7}, {%8,%9}, {%0,%1,%2,%3};"
        : "+f"(d[0]), "+f"(d[1]), "+f"(d[2]), "+f"(d[3])
        : "r"(a[0]), "r"(a[1]), "r"(a[2]), "r"(a[3]), "r"(b0), "r"(b1));
}

// ---------------------------------------------------------------------------
// Prep: 3-way bf16 split of weights, layout [split][m][k].
// ---------------------------------------------------------------------------
__global__ __launch_bounds__(256) void split_kernel(
    const float* __restrict__ wq, const float* __restrict__ wk,
    const float* __restrict__ wv, const float* __restrict__ wp)
{
    int idx = blockIdx.x * 256 + threadIdx.x;
    int m = idx >> 9, k = idx & 511;
    const float* src = (m < 512) ? wq : (m < 1024) ? wk : wv;
    float w = src[(size_t)(m & 511) * 512 + k];
    __nv_bfloat16 h1 = __float2bfloat16(w);
    float r1 = w - __bfloat162float(h1);
    __nv_bfloat16 h2 = __float2bfloat16(r1);
    float r2 = r1 - __bfloat162float(h2);
    __nv_bfloat16 h3 = __float2bfloat16(r2);
    g_wA[(size_t)m * 512 + k]              = h1;
    g_wA[(size_t)(CQKV + m) * 512 + k]     = h2;
    g_wA[(size_t)(2 * CQKV + m) * 512 + k] = h3;
    if (m < 512) {
        float w2 = wp[(size_t)m * 512 + k];
        __nv_bfloat16 p1 = __float2bfloat16(w2);
        float s1 = w2 - __bfloat162float(p1);
        __nv_bfloat16 p2 = __float2bfloat16(s1);
        float s2 = s1 - __bfloat162float(p2);
        __nv_bfloat16 p3 = __float2bfloat16(s2);
        g_wP[(size_t)m * 512 + k]            = p1;
        g_wP[(size_t)(CC + m) * 512 + k]     = p2;
        g_wP[(size_t)(2 * CC + m) * 512 + k] = p3;
    }
}

// ---------------------------------------------------------------------------
// GEMM v4: C[b][M][1024] = sum_s A_s[M][512] @ spikes[b][512][1024].
// Tile 128x256, BK=64, 256 thr, 8 warps (4m x 2n), warp tile 32x128.
// acc[2][16][4] = 128 regs/thread. Double-buffered cp.async (172KB smem).
// Per k-iter per warp: 384 mma vs 56 ldsm (ratio 6.9); 16 syncs/block.
// ---------------------------------------------------------------------------
#define ASTG4 (128 * 144)            // 18432 per A split per stage (64k=128B +16 pad)
#define A3SZ4 (3 * ASTG4)            // 55296
#define BST4  (64 * 512)             // 32768 (row stride 512B, XOR swizzle)
#define STG4  (A3SZ4 + BST4)         // 88064
#define GSM4  (2 * STG4)             // 176128

template<bool EPI>
__global__ __launch_bounds__(256) void gemm4_kernel(
    const __nv_bfloat16* __restrict__ W,     // [3][M][512]
    const __nv_bfloat16* __restrict__ Bsp,   // [BB][512][1024] spikes [c][n]
    float* __restrict__ C, int M,
    const float* __restrict__ bias, const float* __restrict__ bnp)
{
    extern __shared__ __align__(16) char smem[];
    const u32 smemBase = (u32)__cvta_generic_to_shared(smem);

    const int b  = blockIdx.z;
    const int mt = blockIdx.y;
    const int nt = blockIdx.x;
    const int tid  = threadIdx.x;
    const int lane = tid & 31;
    const int warp = tid >> 5;
    const int wm = warp & 3;       // 4 m-warps x 32 rows
    const int wn = warp >> 2;      // 2 n-warps x 128 cols

    const __nv_bfloat16* Bg = Bsp + (size_t)b * (512 * 1024) + nt * 256;

    float acc[2][16][4];
    #pragma unroll
    for (int i = 0; i < 2; i++)
        #pragma unroll
        for (int j = 0; j < 16; j++)
            #pragma unroll
            for (int r = 0; r < 4; r++) acc[i][j][r] = 0.0f;

    auto load_stage = [&](int st, int k0) {
        u32 sb = smemBase + st * STG4;
        #pragma unroll
        for (int j = 0; j < 12; j++) {                 // A: 3072 x 16B
            int idx = j * 256 + tid;
            int s = idx >> 10, rem = idx & 1023;
            int m = rem >> 3, ch = rem & 7;
            cpa16(sb + s * ASTG4 + m * 144 + ch * 16,
                  W + ((size_t)(s * M + mt * 128 + m)) * 512 + k0 + ch * 8);
        }
        #pragma unroll
        for (int j = 0; j < 8; j++) {                  // B: 2048 x 16B
            int idx = j * 256 + tid;
            int br = idx >> 5, bc = idx & 31;
            cpa16(sb + A3SZ4 + br * 512 + ((bc ^ (br & 7)) << 4),
                  Bg + (size_t)(k0 + br) * 1024 + bc * 8);
        }
        cpa_commit();
    };

    load_stage(0, 0);

    for (int kt = 0; kt < 8; kt++) {
        if (kt + 1 < 8) {
            load_stage((kt + 1) & 1, (kt + 1) * 64);
            asm volatile("cp.async.wait_group 1;\n");
        } else {
            asm volatile("cp.async.wait_group 0;\n");
        }
        __syncthreads();

        const u32 aB = smemBase + (kt & 1) * STG4;
        const u32 bB = aB + A3SZ4;

        #pragma unroll
        for (int k16 = 0; k16 < 4; k16++) {
            u32 bfr[8][4];
            #pragma unroll
            for (int ni = 0; ni < 8; ni++) {
                int row = k16 * 16 + (lane & 15);
                int col = wn * 128 + ni * 16 + ((lane >> 4) << 3);
                int c = col >> 3;
                ldsm4t(bfr[ni], bB + row * 512 + ((c ^ (row & 7)) << 4));
            }
            #pragma unroll
            for (int s = 0; s < 3; s++) {
                u32 afr[2][4];
                #pragma unroll
                for (int mi = 0; mi < 2; mi++) {
                    int row = wm * 32 + mi * 16 + (lane & 15);
                    ldsm4(afr[mi], aB + s * ASTG4 + row * 144 + k16 * 32
                                   + ((lane >> 4) << 4));
                }
                #pragma unroll
                for (int mi = 0; mi < 2; mi++)
                    #pragma unroll
                    for (int j = 0; j < 16; j++)
                        mma_bf16(acc[mi][j], afr[mi],
                                 bfr[j >> 1][(j & 1) * 2],
                                 bfr[j >> 1][(j & 1) * 2 + 1]);
            }
        }
        __syncthreads();
    }

    // epilogue
    #pragma unroll
    for (int mi = 0; mi < 2; mi++) {
        #pragma unroll
        for (int r = 0; r < 2; r++) {
            int grow = mt * 128 + wm * 32 + mi * 16 + (lane >> 2) + r * 8;
            float* crow = C + (size_t)b * M * 1024 + (size_t)grow * 1024
                          + nt * 256 + wn * 128 + (lane & 3) * 2;
            float inv = 1.0f, mu = 0.0f, be = 0.0f, bi = 0.0f;
            if (EPI) {
                float g  = bnp[grow];
                be = bnp[512 + grow];
                mu = bnp[1024 + grow];
                float va = bnp[1536 + grow];
                inv = g * rsqrtf(va + 1e-5f);
                bi = bias[grow];
            }
            #pragma unroll
            for (int j = 0; j < 16; j++) {
                float v0 = acc[mi][j][r * 2];
                float v1 = acc[mi][j][r * 2 + 1];
                if (EPI) {
                    v0 = (v0 + bi - mu) * inv + be;
                    v1 = (v1 + bi - mu) * inv + be;
                }
                *(float2*)(crow + j * 8) = make_float2(v0, v1);
            }
        }
    }
}

// ---------------------------------------------------------------------------
// LIF (K1/K5): time-chunked. grid = (rowgroups, 8 chunks), 1 warp/block.
// ---------------------------------------------------------------------------
__global__ __launch_bounds__(32) void lif3_kernel(
    const float* __restrict__ in, const float* __restrict__ bnp,
    __nv_bfloat16* __restrict__ out, float vth)
{
    __shared__ float buf[32][33];
    const int lane = threadIdx.x;
    const int r0   = blockIdx.x * 32;
    const int row  = r0 + lane;
    const int ch   = blockIdx.y;

    float inv = 1.0f, mu = 0.0f, be = 0.0f;
    if (bnp) {
        int c = row & (CC - 1);
        inv = bnp[c] * (1.0f / sqrtf(bnp[3 * CC + c] + 1e-5f));
        be  = bnp[CC + c];
        mu  = bnp[2 * CC + c];
    }

    const int wt     = (ch == 0) ? 0 : (LWM / 32);
    const int ntiles = (LCH / 32) + wt;
    const int start  = ch * LCH - wt * 32;

    const float* src = in + (size_t)r0 * NN;
    __nv_bfloat16* dst = out + (size_t)row * NN;

    float4 nxt[8];
    #pragma unroll
    for (int i = 0; i < 8; i++) {
        int f = lane + 32 * i;
        nxt[i] = *(const float4*)(src + (size_t)(f >> 3) * NN + start + (f & 7) * 4);
    }

    float v = 0.0f;
    for (int t = 0; t < ntiles; t++) {
        #pragma unroll
        for (int i = 0; i < 8; i++) {
            int f = lane + 32 * i;
            int r = f >> 3, c0 = (f & 7) * 4;
            buf[r][c0 + 0] = nxt[i].x;
            buf[r][c0 + 1] = nxt[i].y;
            buf[r][c0 + 2] = nxt[i].z;
            buf[r][c0 + 3] = nxt[i].w;
        }
        __syncwarp();
        if (t + 1 < ntiles) {
            #pragma unroll
            for (int i = 0; i < 8; i++) {
                int f = lane + 32 * i;
                nxt[i] = *(const float4*)(src + (size_t)(f >> 3) * NN
                                          + start + (t + 1) * 32 + (f & 7) * 4);
            }
        }
        u32 pk[16];
        #pragma unroll
        for (int kk = 0; kk < 32; kk++) {
            float x  = buf[lane][kk];
            float xb = (x - mu) * inv + be;
            v = v + (xb - v) * 0.5f;
            bool sp = (v >= vth);
            v = sp ? 0.0f : v;
            u32 sb = sp ? 0x3F80u : 0u;
            if (kk & 1) pk[kk >> 1] |= sb << 16;
            else        pk[kk >> 1]  = sb;
        }
        __syncwarp();
        if (t >= wt) {
            int col = start + t * 32;
            #pragma unroll
            for (int j = 0; j < 4; j++) {
                uint4 q = make_uint4(pk[j*4], pk[j*4+1], pk[j*4+2], pk[j*4+3]);
                *(uint4*)(dst + col + j * 8) = q;
            }
        }
    }
}

// ---------------------------------------------------------------------------
// LIF (K3): time-chunked BN+LIF on QKV output; q -> bf16, k/v -> bitpacked.
// ---------------------------------------------------------------------------
__global__ __launch_bounds__(32) void lif_qkv3_kernel(
    const float* __restrict__ bnq, const float* __restrict__ bnk,
    const float* __restrict__ bnv)
{
    __shared__ float buf[32][33];
    const int lane = threadIdx.x;
    const int r0g  = blockIdx.x * 32;
    const int ch   = blockIdx.y;
    const int b    = r0g / CQKV;
    const int o    = r0g % CQKV;
    const int br   = o >> 9;
    const int c    = (o & 511) + lane;

    const float* bnp = (br == 0) ? bnq : (br == 1) ? bnk : bnv;
    float inv = bnp[c] * (1.0f / sqrtf(bnp[3 * CC + c] + 1e-5f));
    float be  = bnp[CC + c];
    float mu  = bnp[2 * CC + c];

    const int wt     = (ch == 0) ? 0 : (LWM / 32);
    const int ntiles = (LCH / 32) + wt;
    const int start  = ch * LCH - wt * 32;

    const float* src = g_z + (size_t)r0g * NN;
    __nv_bfloat16* qdst = g_sqh + ((size_t)b * CC + c) * NN;
    u64* bdst = ((br == 1) ? g_kb : g_vb) + ((size_t)b * CC + c) * 16;

    float4 nxt[8];
    #pragma unroll
    for (int i = 0; i < 8; i++) {
        int f = lane + 32 * i;
        nxt[i] = *(const float4*)(src + (size_t)(f >> 3) * NN + start + (f & 7) * 4);
    }

    float v = 0.0f;
    u32 prevbits = 0;
    for (int t = 0; t < ntiles; t++) {
        #pragma unroll
        for (int i = 0; i < 8; i++) {
            int f = lane + 32 * i;
            int r = f >> 3, cc = (f & 7) * 4;
            buf[r][cc + 0] = nxt[i].x;
            buf[r][cc + 1] = nxt[i].y;
            buf[r][cc + 2] = nxt[i].z;
            buf[r][cc + 3] = nxt[i].w;
        }
        __syncwarp();
        if (t + 1 < ntiles) {
            #pragma unroll
            for (int i = 0; i < 8; i++) {
                int f = lane + 32 * i;
                nxt[i] = *(const float4*)(src + (size_t)(f >> 3) * NN
                                          + start + (t + 1) * 32 + (f & 7) * 4);
            }
        }
        u32 pk[16];
        u32 tb = 0;
        #pragma unroll
        for (int kk = 0; kk < 32; kk++) {
            float x  = buf[lane][kk];
            float xb = (x - mu) * inv + be;
            v = v + (xb - v) * 0.5f;
            bool sp = (v >= 1.0f);
            v = sp ? 0.0f : v;
            if (br == 0) {
                u32 sbv = sp ? 0x3F80u : 0u;
                if (kk & 1) pk[kk >> 1] |= sbv << 16;
                else        pk[kk >> 1]  = sbv;
            } else {
                tb |= (sp ? 1u : 0u) << kk;
            }
        }
        __syncwarp();
        if (t >= wt) {
            int et  = t - wt;
            int col = ch * LCH + et * 32;
            if (br == 0) {
                #pragma unroll
                for (int j = 0; j < 4; j++) {
                    uint4 q = make_uint4(pk[j*4], pk[j*4+1], pk[j*4+2], pk[j*4+3]);
                    *(uint4*)(qdst + col + j * 8) = q;
                }
            } else {
                if (et & 1) bdst[ch * 2 + (et >> 1)] = ((u64)tb << 32) | (u64)prevbits;
                else        prevbits = tb;
            }
        }
    }
}

// ---------------------------------------------------------------------------
// attn: y = q @ (k^T v) * 0.25 per (b,h); d-split x2, n-split x8.
// ---------------------------------------------------------------------------
__global__ __launch_bounds__(128) void attn3_kernel()
{
    __shared__ u64 kbs[64][16];
    __shared__ u64 vbs[32][16];
    __shared__ __align__(16) float Gs[64][32];

    const int nc = blockIdx.x;
    const int h  = blockIdx.y >> 1;
    const int dh = blockIdx.y & 1;
    const int b  = blockIdx.z;
    const int tid = threadIdx.x;
    const size_t base_c = (size_t)b * CC + h * DD;

    for (int i = tid; i < 64 * 16; i += 128) {
        int d = i >> 4, j = i & 15;
        kbs[d][j] = g_kb[(base_c + d) * 16 + j];
    }
    for (int i = tid; i < 32 * 16; i += 128) {
        int d = i >> 4, j = i & 15;
        vbs[d][j] = g_vb[(base_c + dh * 32 + d) * 16 + j];
    }
    __syncthreads();

    for (int e = tid; e < 64 * 32; e += 128) {
        int dp = e >> 5, dd = e & 31;
        int gsum = 0;
        #pragma unroll
        for (int j = 0; j < 16; j++)
            gsum += __popcll(kbs[dp][j] & vbs[dd][j]);
        Gs[dp][dd] = (float)gsum;
    }
    __syncthreads();

    const int n = nc * 128 + tid;
    const __nv_bfloat16* qb = g_sqh + base_c * NN + n;

    float acc[32];
    #pragma unroll
    for (int d = 0; d < 32; d++) acc[d] = 0.0f;

    #pragma unroll 4
    for (int dp = 0; dp < 64; dp++) {
        float qv = __bfloat162float(qb[(size_t)dp * NN]);
        const float4* gr = (const float4*)&Gs[dp][0];
        #pragma unroll
        for (int j = 0; j < 8; j++) {
            float4 g4 = gr[j];
            acc[j * 4 + 0] += qv * g4.x;
            acc[j * 4 + 1] += qv * g4.y;
            acc[j * 4 + 2] += qv * g4.z;
            acc[j * 4 + 3] += qv * g4.w;
        }
    }
    #pragma unroll
    for (int d = 0; d < 32; d++)
        g_y[(base_c + dh * 32 + d) * NN + n] = acc[d] * 0.25f;
}

// ---------------------------------------------------------------------------
// Launch
// ---------------------------------------------------------------------------
extern "C" void kernel_launch(void* const* d_in, const int* in_sizes, int n_in,
                              void* d_out, int out_size)
{
    const float* x       = (const float*)d_in[0];
    const float* bn_pre  = (const float*)d_in[1];
    const float* w_q     = (const float*)d_in[2];
    const float* bn_q    = (const float*)d_in[3];
    const float* w_k     = (const float*)d_in[4];
    const float* bn_k    = (const float*)d_in[5];
    const float* w_v     = (const float*)d_in[6];
    const float* bn_v    = (const float*)d_in[7];
    const float* w_proj  = (const float*)d_in[8];
    const float* b_proj  = (const float*)d_in[9];
    const float* bn_proj = (const float*)d_in[10];
    float* out = (float*)d_out;

    __nv_bfloat16* xq_ptr; cudaGetSymbolAddress((void**)&xq_ptr, g_xq);
    __nv_bfloat16* sy_ptr; cudaGetSymbolAddress((void**)&sy_ptr, g_sy);
    __nv_bfloat16* wA_ptr; cudaGetSymbolAddress((void**)&wA_ptr, g_wA);
    __nv_bfloat16* wP_ptr; cudaGetSymbolAddress((void**)&wP_ptr, g_wP);
    float* z_ptr;  cudaGetSymbolAddress((void**)&z_ptr, g_z);
    float* y_ptr;  cudaGetSymbolAddress((void**)&y_ptr, g_y);

    cudaFuncSetAttribute(gemm4_kernel<false>,
                         cudaFuncAttributeMaxDynamicSharedMemorySize, GSM4);
    cudaFuncSetAttribute(gemm4_kernel<true>,
                         cudaFuncAttributeMaxDynamicSharedMemorySize, GSM4);

    // P0: 3-way bf16 weight splits, [s][m][k]
    split_kernel<<<(CQKV * CC) / 256, 256>>>(w_q, w_k, w_v, w_proj);

    // K1: pre BN + LIF -> xq spikes (bf16 [b][c][n]), time-chunked
    lif3_kernel<<<dim3((BB * CC) / 32, NN / LCH), 32>>>(x, bn_pre, xq_ptr, 1.0f);

    // K2: fused QKV GEMM (bf16 HMMA, 128x256xBK64)
    gemm4_kernel<false><<<dim3(NN / 256, CQKV / 128, BB), 256, GSM4>>>(
        wA_ptr, xq_ptr, z_ptr, CQKV, nullptr, nullptr);

    // K3: per-branch BN + LIF (time-chunked); q -> bf16, k/v -> bitpacked
    lif_qkv3_kernel<<<dim3((BB * CQKV) / 32, NN / LCH), 32>>>(bn_q, bn_k, bn_v);

    // K4: linear attention via G = k^T v (popcount), y = q G * 0.25
    attn3_kernel<<<dim3(8, 16, 8), 128>>>();

    // K5: attn LIF (threshold 0.5) -> sy spikes (bf16 [b][c][n]), time-chunked
    lif3_kernel<<<dim3((BB * CC) / 32, NN / LCH), 32>>>(y_ptr, nullptr, sy_ptr, 0.5f);

    // K6: projection GEMM + bias + bn_proj fused epilogue -> out
    gemm4_kernel<true><<<dim3(NN / 256, CC / 128, BB), 256, GSM4>>>(
        wP_ptr, sy_ptr, out, CC, b_proj, bn_proj);
}

// round 16
// speedup vs baseline: 3.2901x; 1.1863x over previous
#include <cuda_runtime.h>
#include <cuda_bf16.h>
#include <cuda_fp16.h>
#include <cstdint>

typedef unsigned long long u64;
typedef unsigned int u32;

// Shapes (fixed by the problem)
#define BB    8
#define CC    512
#define NN    1024
#define HH    8
#define DD    64
#define CQKV  1536

// LIF time-chunking: 8 chunks of 128 steps, 64-step warmup
#define LCH   128
#define LWM   64

// ---------------------------------------------------------------------------
// Device scratch
// ---------------------------------------------------------------------------
__device__ __half g_xq1[BB * CC * NN];               // pre-LIF spikes, fp16 1.0
__device__ __half g_xq2[BB * CC * NN];               // pre-LIF spikes, fp16 2^-12
__device__ float g_z [BB * CQKV * NN];               // Wqkv @ xq, [b][o][n]
__device__ __nv_bfloat16 g_sqh[BB * CC * NN];        // q spikes bf16, [b][c][n]
__device__ u64 g_kb[BB * CC * 16];                   // k spikes bitpacked along n
__device__ u64 g_vb[BB * CC * 16];                   // v spikes bitpacked along n
__device__ float g_y [BB * CC * NN];                 // attention out * 0.25
__device__ __half g_sy1[BB * CC * NN];               // attn LIF spikes, fp16 1.0
__device__ __half g_sy2[BB * CC * NN];               // attn LIF spikes, fp16 2^-12
__device__ __half g_hA[2 * CQKV * CC];               // [2][1536][512] qkv fp16 splits
__device__ __half g_hP[2 * CC * CC];                 // [2][512][512]  proj fp16 splits

// ---------------------------------------------------------------------------
// PTX helpers
// ---------------------------------------------------------------------------
__device__ __forceinline__ void cpa16(u32 dst, const void* src) {
    asm volatile("cp.async.cg.shared.global [%0], [%1], 16;\n" :: "r"(dst), "l"(src));
}
__device__ __forceinline__ void cpa_commit() {
    asm volatile("cp.async.commit_group;\n");
}
__device__ __forceinline__ void ldsm4(u32* r, u32 addr) {
    asm volatile("ldmatrix.sync.aligned.m8n8.x4.shared.b16 {%0,%1,%2,%3}, [%4];"
        : "=r"(r[0]), "=r"(r[1]), "=r"(r[2]), "=r"(r[3]) : "r"(addr));
}
__device__ __forceinline__ void ldsm4t(u32* r, u32 addr) {
    asm volatile("ldmatrix.sync.aligned.m8n8.x4.trans.shared.b16 {%0,%1,%2,%3}, [%4];"
        : "=r"(r[0]), "=r"(r[1]), "=r"(r[2]), "=r"(r[3]) : "r"(addr));
}
__device__ __forceinline__ void mma_f16(float* d, const u32* a, u32 b0, u32 b1) {
    asm volatile(
        "mma.sync.aligned.m16n8k16.row.col.f32.f16.f16.f32 "
        "{%0,%1,%2,%3}, {%4,%5,%6,%7}, {%8,%9}, {%0,%1,%2,%3};"
        : "+f"(d[0]), "+f"(d[1]), "+f"(d[2]), "+f"(d[3])
        : "r"(a[0]), "r"(a[1]), "r"(a[2]), "r"(a[3]), "r"(b0), "r"(b1));
}

// ---------------------------------------------------------------------------
// Prep: 2-way fp16 split: w = h1 + 2^-12 * f2, residual <= 2^-24 |w|.
// Layout [split][m][k].
// ---------------------------------------------------------------------------
__global__ __launch_bounds__(256) void split_kernel(
    const float* __restrict__ wq, const float* __restrict__ wk,
    const float* __restrict__ wv, const float* __restrict__ wp)
{
    int idx = blockIdx.x * 256 + threadIdx.x;
    int m = idx >> 9, k = idx & 511;
    const float* src = (m < 512) ? wq : (m < 1024) ? wk : wv;
    float w = src[(size_t)(m & 511) * 512 + k];
    __half h1 = __float2half_rn(w);
    float r1 = w - __half2float(h1);
    __half f2 = __float2half_rn(r1 * 4096.0f);
    g_hA[(size_t)m * 512 + k]          = h1;
    g_hA[(size_t)(CQKV + m) * 512 + k] = f2;
    if (m < 512) {
        float w2 = wp[(size_t)m * 512 + k];
        __half p1 = __float2half_rn(w2);
        float s1 = w2 - __half2float(p1);
        __half p2 = __float2half_rn(s1 * 4096.0f);
        g_hP[(size_t)m * 512 + k]        = p1;
        g_hP[(size_t)(CC + m) * 512 + k] = p2;
    }
}

// ---------------------------------------------------------------------------
// GEMM v5: C[b][M][1024] = (H1[M][512] @ S1) + (F2[M][512] @ S2)
// where S1 = spikes * 1.0 (fp16), S2 = spikes * 2^-12 (fp16): both splits
// chain into the SAME fp32 acc, no rescale. Tile 128x256, BK=64, 256 thr,
// 8 warps (4m x 2n), warp tile 32x128, double-buffered cp.async, 204.8KB smem.
// ---------------------------------------------------------------------------
#define ASTG5 (128 * 144)            // 18432 per A split per stage
#define A2SZ5 (2 * ASTG5)            // 36864
#define BVER5 (64 * 512)             // 32768 per B version
#define STG5  (A2SZ5 + 2 * BVER5)    // 102400
#define GSM5  (2 * STG5)             // 204800

template<bool EPI>
__global__ __launch_bounds__(256) void gemm5_kernel(
    const __half* __restrict__ W,        // [2][M][512]
    const __half* __restrict__ B1,       // [BB][512][1024] spikes * 1.0
    const __half* __restrict__ B2,       // [BB][512][1024] spikes * 2^-12
    float* __restrict__ C, int M,
    const float* __restrict__ bias, const float* __restrict__ bnp)
{
    extern __shared__ __align__(16) char smem[];
    const u32 smemBase = (u32)__cvta_generic_to_shared(smem);

    const int b  = blockIdx.z;
    const int mt = blockIdx.y;
    const int nt = blockIdx.x;
    const int tid  = threadIdx.x;
    const int lane = tid & 31;
    const int warp = tid >> 5;
    const int wm = warp & 3;       // 4 m-warps x 32 rows
    const int wn = warp >> 2;      // 2 n-warps x 128 cols

    const __half* Bg1 = B1 + (size_t)b * (512 * 1024) + nt * 256;
    const __half* Bg2 = B2 + (size_t)b * (512 * 1024) + nt * 256;

    float acc[2][16][4];
    #pragma unroll
    for (int i = 0; i < 2; i++)
        #pragma unroll
        for (int j = 0; j < 16; j++)
            #pragma unroll
            for (int r = 0; r < 4; r++) acc[i][j][r] = 0.0f;

    auto load_stage = [&](int st, int k0) {
        u32 sb = smemBase + st * STG5;
        #pragma unroll
        for (int j = 0; j < 8; j++) {                  // A: 2048 x 16B
            int idx = j * 256 + tid;
            int s = idx >> 10, rem = idx & 1023;
            int m = rem >> 3, ch = rem & 7;
            cpa16(sb + s * ASTG5 + m * 144 + ch * 16,
                  W + ((size_t)(s * M + mt * 128 + m)) * 512 + k0 + ch * 8);
        }
        #pragma unroll
        for (int j = 0; j < 8; j++) {                  // B1: 2048 x 16B
            int idx = j * 256 + tid;
            int br = idx >> 5, bc = idx & 31;
            cpa16(sb + A2SZ5 + br * 512 + ((bc ^ (br & 7)) << 4),
                  Bg1 + (size_t)(k0 + br) * 1024 + bc * 8);
        }
        #pragma unroll
        for (int j = 0; j < 8; j++) {                  // B2: 2048 x 16B
            int idx = j * 256 + tid;
            int br = idx >> 5, bc = idx & 31;
            cpa16(sb + A2SZ5 + BVER5 + br * 512 + ((bc ^ (br & 7)) << 4),
                  Bg2 + (size_t)(k0 + br) * 1024 + bc * 8);
        }
        cpa_commit();
    };

    load_stage(0, 0);

    for (int kt = 0; kt < 8; kt++) {
        if (kt + 1 < 8) {
            load_stage((kt + 1) & 1, (kt + 1) * 64);
            asm volatile("cp.async.wait_group 1;\n");
        } else {
            asm volatile("cp.async.wait_group 0;\n");
        }
        __syncthreads();

        const u32 aB = smemBase + (kt & 1) * STG5;

        #pragma unroll
        for (int k16 = 0; k16 < 4; k16++) {
            #pragma unroll
            for (int s = 0; s < 2; s++) {
                const u32 bB = aB + A2SZ5 + s * BVER5;
                u32 bfr[8][4];
                #pragma unroll
                for (int ni = 0; ni < 8; ni++) {
                    int row = k16 * 16 + (lane & 15);
                    int col = wn * 128 + ni * 16 + ((lane >> 4) << 3);
                    int c = col >> 3;
                    ldsm4t(bfr[ni], bB + row * 512 + ((c ^ (row & 7)) << 4));
                }
                u32 afr[2][4];
                #pragma unroll
                for (int mi = 0; mi < 2; mi++) {
                    int row = wm * 32 + mi * 16 + (lane & 15);
                    ldsm4(afr[mi], aB + s * ASTG5 + row * 144 + k16 * 32
                                   + ((lane >> 4) << 4));
                }
                #pragma unroll
                for (int mi = 0; mi < 2; mi++)
                    #pragma unroll
                    for (int j = 0; j < 16; j++)
                        mma_f16(acc[mi][j], afr[mi],
                                bfr[j >> 1][(j & 1) * 2],
                                bfr[j >> 1][(j & 1) * 2 + 1]);
            }
        }
        __syncthreads();
    }

    // epilogue
    #pragma unroll
    for (int mi = 0; mi < 2; mi++) {
        #pragma unroll
        for (int r = 0; r < 2; r++) {
            int grow = mt * 128 + wm * 32 + mi * 16 + (lane >> 2) + r * 8;
            float* crow = C + (size_t)b * M * 1024 + (size_t)grow * 1024
                          + nt * 256 + wn * 128 + (lane & 3) * 2;
            float inv = 1.0f, mu = 0.0f, be = 0.0f, bi = 0.0f;
            if (EPI) {
                float g  = bnp[grow];
                be = bnp[512 + grow];
                mu = bnp[1024 + grow];
                float va = bnp[1536 + grow];
                inv = g * rsqrtf(va + 1e-5f);
                bi = bias[grow];
            }
            #pragma unroll
            for (int j = 0; j < 16; j++) {
                float v0 = acc[mi][j][r * 2];
                float v1 = acc[mi][j][r * 2 + 1];
                if (EPI) {
                    v0 = (v0 + bi - mu) * inv + be;
                    v1 = (v1 + bi - mu) * inv + be;
                }
                *(float2*)(crow + j * 8) = make_float2(v0, v1);
            }
        }
    }
}

// ---------------------------------------------------------------------------
// LIF (K1/K5): time-chunked, DUAL fp16 spike outputs (1.0 and 2^-12).
// pk2 = pk1 & 0x0C000C00 (0x3C00 & 0x0C00 == 0x0C00).
// ---------------------------------------------------------------------------
__global__ __launch_bounds__(32) void lif3d_kernel(
    const float* __restrict__ in, const float* __restrict__ bnp,
    __half* __restrict__ out1, __half* __restrict__ out2, float vth)
{
    __shared__ float buf[32][33];
    const int lane = threadIdx.x;
    const int r0   = blockIdx.x * 32;
    const int row  = r0 + lane;
    const int ch   = blockIdx.y;

    float inv = 1.0f, mu = 0.0f, be = 0.0f;
    if (bnp) {
        int c = row & (CC - 1);
        inv = bnp[c] * (1.0f / sqrtf(bnp[3 * CC + c] + 1e-5f));
        be  = bnp[CC + c];
        mu  = bnp[2 * CC + c];
    }

    const int wt     = (ch == 0) ? 0 : (LWM / 32);
    const int ntiles = (LCH / 32) + wt;
    const int start  = ch * LCH - wt * 32;

    const float* src = in + (size_t)r0 * NN;
    __half* dst1 = out1 + (size_t)row * NN;
    __half* dst2 = out2 + (size_t)row * NN;

    float4 nxt[8];
    #pragma unroll
    for (int i = 0; i < 8; i++) {
        int f = lane + 32 * i;
        nxt[i] = *(const float4*)(src + (size_t)(f >> 3) * NN + start + (f & 7) * 4);
    }

    float v = 0.0f;
    for (int t = 0; t < ntiles; t++) {
        #pragma unroll
        for (int i = 0; i < 8; i++) {
            int f = lane + 32 * i;
            int r = f >> 3, c0 = (f & 7) * 4;
            buf[r][c0 + 0] = nxt[i].x;
            buf[r][c0 + 1] = nxt[i].y;
            buf[r][c0 + 2] = nxt[i].z;
            buf[r][c0 + 3] = nxt[i].w;
        }
        __syncwarp();
        if (t + 1 < ntiles) {
            #pragma unroll
            for (int i = 0; i < 8; i++) {
                int f = lane + 32 * i;
                nxt[i] = *(const float4*)(src + (size_t)(f >> 3) * NN
                                          + start + (t + 1) * 32 + (f & 7) * 4);
            }
        }
        u32 pk[16];
        #pragma unroll
        for (int kk = 0; kk < 32; kk++) {
            float x  = buf[lane][kk];
            float xb = (x - mu) * inv + be;
            v = v + (xb - v) * 0.5f;
            bool sp = (v >= vth);
            v = sp ? 0.0f : v;
            u32 sb = sp ? 0x3C00u : 0u;                // fp16 1.0
            if (kk & 1) pk[kk >> 1] |= sb << 16;
            else        pk[kk >> 1]  = sb;
        }
        __syncwarp();
        if (t >= wt) {
            int col = start + t * 32;
            #pragma unroll
            for (int j = 0; j < 4; j++) {
                uint4 q1 = make_uint4(pk[j*4], pk[j*4+1], pk[j*4+2], pk[j*4+3]);
                uint4 q2 = make_uint4(pk[j*4]   & 0x0C000C00u,
                                      pk[j*4+1] & 0x0C000C00u,
                                      pk[j*4+2] & 0x0C000C00u,
                                      pk[j*4+3] & 0x0C000C00u);
                *(uint4*)(dst1 + col + j * 8) = q1;
                *(uint4*)(dst2 + col + j * 8) = q2;
            }
        }
    }
}

// ---------------------------------------------------------------------------
// LIF (K3): time-chunked BN+LIF on QKV output; q -> bf16, k/v -> bitpacked.
// (unchanged from R15)
// ---------------------------------------------------------------------------
__global__ __launch_bounds__(32) void lif_qkv3_kernel(
    const float* __restrict__ bnq, const float* __restrict__ bnk,
    const float* __restrict__ bnv)
{
    __shared__ float buf[32][33];
    const int lane = threadIdx.x;
    const int r0g  = blockIdx.x * 32;
    const int ch   = blockIdx.y;
    const int b    = r0g / CQKV;
    const int o    = r0g % CQKV;
    const int br   = o >> 9;
    const int c    = (o & 511) + lane;

    const float* bnp = (br == 0) ? bnq : (br == 1) ? bnk : bnv;
    float inv = bnp[c] * (1.0f / sqrtf(bnp[3 * CC + c] + 1e-5f));
    float be  = bnp[CC + c];
    float mu  = bnp[2 * CC + c];

    const int wt     = (ch == 0) ? 0 : (LWM / 32);
    const int ntiles = (LCH / 32) + wt;
    const int start  = ch * LCH - wt * 32;

    const float* src = g_z + (size_t)r0g * NN;
    __nv_bfloat16* qdst = g_sqh + ((size_t)b * CC + c) * NN;
    u64* bdst = ((br == 1) ? g_kb : g_vb) + ((size_t)b * CC + c) * 16;

    float4 nxt[8];
    #pragma unroll
    for (int i = 0; i < 8; i++) {
        int f = lane + 32 * i;
        nxt[i] = *(const float4*)(src + (size_t)(f >> 3) * NN + start + (f & 7) * 4);
    }

    float v = 0.0f;
    u32 prevbits = 0;
    for (int t = 0; t < ntiles; t++) {
        #pragma unroll
        for (int i = 0; i < 8; i++) {
            int f = lane + 32 * i;
            int r = f >> 3, cc = (f & 7) * 4;
            buf[r][cc + 0] = nxt[i].x;
            buf[r][cc + 1] = nxt[i].y;
            buf[r][cc + 2] = nxt[i].z;
            buf[r][cc + 3] = nxt[i].w;
        }
        __syncwarp();
        if (t + 1 < ntiles) {
            #pragma unroll
            for (int i = 0; i < 8; i++) {
                int f = lane + 32 * i;
                nxt[i] = *(const float4*)(src + (size_t)(f >> 3) * NN
                                          + start + (t + 1) * 32 + (f & 7) * 4);
            }
        }
        u32 pk[16];
        u32 tb = 0;
        #pragma unroll
        for (int kk = 0; kk < 32; kk++) {
            float x  = buf[lane][kk];
            float xb = (x - mu) * inv + be;
            v = v + (xb - v) * 0.5f;
            bool sp = (v >= 1.0f);
            v = sp ? 0.0f : v;
            if (br == 0) {
                u32 sbv = sp ? 0x3F80u : 0u;
                if (kk & 1) pk[kk >> 1] |= sbv << 16;
                else        pk[kk >> 1]  = sbv;
            } else {
                tb |= (sp ? 1u : 0u) << kk;
            }
        }
        __syncwarp();
        if (t >= wt) {
            int et  = t - wt;
            int col = ch * LCH + et * 32;
            if (br == 0) {
                #pragma unroll
                for (int j = 0; j < 4; j++) {
                    uint4 q = make_uint4(pk[j*4], pk[j*4+1], pk[j*4+2], pk[j*4+3]);
                    *(uint4*)(qdst + col + j * 8) = q;
                }
            } else {
                if (et & 1) bdst[ch * 2 + (et >> 1)] = ((u64)tb << 32) | (u64)prevbits;
                else        prevbits = tb;
            }
        }
    }
}

// ---------------------------------------------------------------------------
// attn: y = q @ (k^T v) * 0.25 per (b,h); d-split x2, n-split x8. (unchanged)
// ---------------------------------------------------------------------------
__global__ __launch_bounds__(128) void attn3_kernel()
{
    __shared__ u64 kbs[64][16];
    __shared__ u64 vbs[32][16];
    __shared__ __align__(16) float Gs[64][32];

    const int nc = blockIdx.x;
    const int h  = blockIdx.y >> 1;
    const int dh = blockIdx.y & 1;
    const int b  = blockIdx.z;
    const int tid = threadIdx.x;
    const size_t base_c = (size_t)b * CC + h * DD;

    for (int i = tid; i < 64 * 16; i += 128) {
        int d = i >> 4, j = i & 15;
        kbs[d][j] = g_kb[(base_c + d) * 16 + j];
    }
    for (int i = tid; i < 32 * 16; i += 128) {
        int d = i >> 4, j = i & 15;
        vbs[d][j] = g_vb[(base_c + dh * 32 + d) * 16 + j];
    }
    __syncthreads();

    for (int e = tid; e < 64 * 32; e += 128) {
        int dp = e >> 5, dd = e & 31;
        int gsum = 0;
        #pragma unroll
        for (int j = 0; j < 16; j++)
            gsum += __popcll(kbs[dp][j] & vbs[dd][j]);
        Gs[dp][dd] = (float)gsum;
    }
    __syncthreads();

    const int n = nc * 128 + tid;
    const __nv_bfloat16* qb = g_sqh + base_c * NN + n;

    float acc[32];
    #pragma unroll
    for (int d = 0; d < 32; d++) acc[d] = 0.0f;

    #pragma unroll 4
    for (int dp = 0; dp < 64; dp++) {
        float qv = __bfloat162float(qb[(size_t)dp * NN]);
        const float4* gr = (const float4*)&Gs[dp][0];
        #pragma unroll
        for (int j = 0; j < 8; j++) {
            float4 g4 = gr[j];
            acc[j * 4 + 0] += qv * g4.x;
            acc[j * 4 + 1] += qv * g4.y;
            acc[j * 4 + 2] += qv * g4.z;
            acc[j * 4 + 3] += qv * g4.w;
        }
    }
    #pragma unroll
    for (int d = 0; d < 32; d++)
        g_y[(base_c + dh * 32 + d) * NN + n] = acc[d] * 0.25f;
}

// ---------------------------------------------------------------------------
// Launch
// ---------------------------------------------------------------------------
extern "C" void kernel_launch(void* const* d_in, const int* in_sizes, int n_in,
                              void* d_out, int out_size)
{
    const float* x       = (const float*)d_in[0];
    const float* bn_pre  = (const float*)d_in[1];
    const float* w_q     = (const float*)d_in[2];
    const float* bn_q    = (const float*)d_in[3];
    const float* w_k     = (const float*)d_in[4];
    const float* bn_k    = (const float*)d_in[5];
    const float* w_v     = (const float*)d_in[6];
    const float* bn_v    = (const float*)d_in[7];
    const float* w_proj  = (const float*)d_in[8];
    const float* b_proj  = (const float*)d_in[9];
    const float* bn_proj = (const float*)d_in[10];
    float* out = (float*)d_out;

    __half* xq1_ptr; cudaGetSymbolAddress((void**)&xq1_ptr, g_xq1);
    __half* xq2_ptr; cudaGetSymbolAddress((void**)&xq2_ptr, g_xq2);
    __half* sy1_ptr; cudaGetSymbolAddress((void**)&sy1_ptr, g_sy1);
    __half* sy2_ptr; cudaGetSymbolAddress((void**)&sy2_ptr, g_sy2);
    __half* hA_ptr;  cudaGetSymbolAddress((void**)&hA_ptr, g_hA);
    __half* hP_ptr;  cudaGetSymbolAddress((void**)&hP_ptr, g_hP);
    float* z_ptr;  cudaGetSymbolAddress((void**)&z_ptr, g_z);
    float* y_ptr;  cudaGetSymbolAddress((void**)&y_ptr, g_y);

    cudaFuncSetAttribute(gemm5_kernel<false>,
                         cudaFuncAttributeMaxDynamicSharedMemorySize, GSM5);
    cudaFuncSetAttribute(gemm5_kernel<true>,
                         cudaFuncAttributeMaxDynamicSharedMemorySize, GSM5);

    // P0: 2-way fp16 weight splits, [s][m][k]
    split_kernel<<<(CQKV * CC) / 256, 256>>>(w_q, w_k, w_v, w_proj);

    // K1: pre BN + LIF -> xq spikes (dual fp16), time-chunked
    lif3d_kernel<<<dim3((BB * CC) / 32, NN / LCH), 32>>>(
        x, bn_pre, xq1_ptr, xq2_ptr, 1.0f);

    // K2: fused QKV GEMM (fp16 HMMA, 2-split dual-B)
    gemm5_kernel<false><<<dim3(NN / 256, CQKV / 128, BB), 256, GSM5>>>(
        hA_ptr, xq1_ptr, xq2_ptr, z_ptr, CQKV, nullptr, nullptr);

    // K3: per-branch BN + LIF (time-chunked); q -> bf16, k/v -> bitpacked
    lif_qkv3_kernel<<<dim3((BB * CQKV) / 32, NN / LCH), 32>>>(bn_q, bn_k, bn_v);

    // K4: linear attention via G = k^T v (popcount), y = q G * 0.25
    attn3_kernel<<<dim3(8, 16, 8), 128>>>();

    // K5: attn LIF (threshold 0.5) -> sy spikes (dual fp16), time-chunked
    lif3d_kernel<<<dim3((BB * CC) / 32, NN / LCH), 32>>>(
        y_ptr, nullptr, sy1_ptr, sy2_ptr, 0.5f);

    // K6: projection GEMM + bias + bn_proj fused epilogue -> out
    gemm5_kernel<true><<<dim3(NN / 256, CC / 128, BB), 256, GSM5>>>(
        hP_ptr, sy1_ptr, sy2_ptr, out, CC, b_proj, bn_proj);
}

// round 17
// speedup vs baseline: 3.3998x; 1.0333x over previous
#include <cuda_runtime.h>
#include <cuda_bf16.h>
#include <cuda_fp16.h>
#include <cstdint>

typedef unsigned long long u64;
typedef unsigned int u32;

// Shapes (fixed by the problem)
#define BB    8
#define CC    512
#define NN    1024
#define HH    8
#define DD    64
#define CQKV  1536

// LIF time-chunking: 8 chunks of 128 steps, 64-step warmup
#define LCH   128
#define LWM   64

// ---------------------------------------------------------------------------
// Device scratch
// ---------------------------------------------------------------------------
__device__ __half g_xq[BB * CC * NN];                // pre-LIF spikes, fp16 {0,1}
__device__ float g_z [BB * CQKV * NN];               // Wqkv @ xq, [b][o][n]
__device__ __nv_bfloat16 g_sqh[BB * CC * NN];        // q spikes bf16, [b][c][n]
__device__ u64 g_kb[BB * CC * 16];                   // k spikes bitpacked along n
__device__ u64 g_vb[BB * CC * 16];                   // v spikes bitpacked along n
__device__ float g_y [BB * CC * NN];                 // attention out * 0.25
__device__ __half g_sy[BB * CC * NN];                // attn LIF spikes, fp16 {0,1}
__device__ __half g_hA[2 * CQKV * CC];               // [2][1536][512] qkv fp16 splits
__device__ __half g_hP[2 * CC * CC];                 // [2][512][512]  proj fp16 splits

// ---------------------------------------------------------------------------
// PTX helpers
// ---------------------------------------------------------------------------
__device__ __forceinline__ void cpa16(u32 dst, const void* src) {
    asm volatile("cp.async.cg.shared.global [%0], [%1], 16;\n" :: "r"(dst), "l"(src));
}
__device__ __forceinline__ void cpa_commit() {
    asm volatile("cp.async.commit_group;\n");
}
__device__ __forceinline__ void ldsm4(u32* r, u32 addr) {
    asm volatile("ldmatrix.sync.aligned.m8n8.x4.shared.b16 {%0,%1,%2,%3}, [%4];"
        : "=r"(r[0]), "=r"(r[1]), "=r"(r[2]), "=r"(r[3]) : "r"(addr));
}
__device__ __forceinline__ void ldsm4t(u32* r, u32 addr) {
    asm volatile("ldmatrix.sync.aligned.m8n8.x4.trans.shared.b16 {%0,%1,%2,%3}, [%4];"
        : "=r"(r[0]), "=r"(r[1]), "=r"(r[2]), "=r"(r[3]) : "r"(addr));
}
__device__ __forceinline__ void mma_f16(float* d, const u32* a, u32 b0, u32 b1) {
    asm volatile(
        "mma.sync.aligned.m16n8k16.row.col.f32.f16.f16.f32 "
        "{%0,%1,%2,%3}, {%4,%5,%6,%7}, {%8,%9}, {%0,%1,%2,%3};"
        : "+f"(d[0]), "+f"(d[1]), "+f"(d[2]), "+f"(d[3])
        : "r"(a[0]), "r"(a[1]), "r"(a[2]), "r"(a[3]), "r"(b0), "r"(b1));
}

// ---------------------------------------------------------------------------
// Prep: 2-way fp16 split: w = h1 + 2^-12 * f2, residual <= 2^-24 |w|.
// Layout [split][m][k].
// ---------------------------------------------------------------------------
__global__ __launch_bounds__(256) void split_kernel(
    const float* __restrict__ wq, const float* __restrict__ wk,
    const float* __restrict__ wv, const float* __restrict__ wp)
{
    int idx = blockIdx.x * 256 + threadIdx.x;
    int m = idx >> 9, k = idx & 511;
    const float* src = (m < 512) ? wq : (m < 1024) ? wk : wv;
    float w = src[(size_t)(m & 511) * 512 + k];
    __half h1 = __float2half_rn(w);
    float r1 = w - __half2float(h1);
    __half f2 = __float2half_rn(r1 * 4096.0f);
    g_hA[(size_t)m * 512 + k]          = h1;
    g_hA[(size_t)(CQKV + m) * 512 + k] = f2;
    if (m < 512) {
        float w2 = wp[(size_t)m * 512 + k];
        __half p1 = __float2half_rn(w2);
        float s1 = w2 - __half2float(p1);
        __half p2 = __float2half_rn(s1 * 4096.0f);
        g_hP[(size_t)m * 512 + k]        = p1;
        g_hP[(size_t)(CC + m) * 512 + k] = p2;
    }
}

// ---------------------------------------------------------------------------
// GEMM v6: C = H1 @ S + F2 @ (S & 0x0C00-mask), ONE B array.
// Split-2 B fragments derived in registers: fp16 1.0 (0x3C00) AND 0x0C00
// = 2^-12 exactly; zero stays zero. Bit-identical to R16's dual-B version.
// Tile 128x256, BK=64, 256 thr, 8 warps (4m x 2n), warp tile 32x128.
// Double-buffered cp.async, 139.3KB smem.
// ---------------------------------------------------------------------------
#define ASTG6 (128 * 144)            // 18432 per A split per stage
#define A2SZ6 (2 * ASTG6)            // 36864
#define BST6  (64 * 512)             // 32768 single B version
#define STG6  (A2SZ6 + BST6)         // 69632
#define GSM6  (2 * STG6)             // 139264

template<bool EPI>
__global__ __launch_bounds__(256) void gemm6_kernel(
    const __half* __restrict__ W,        // [2][M][512]
    const __half* __restrict__ Bsp,      // [BB][512][1024] spikes fp16 {0,1}
    float* __restrict__ C, int M,
    const float* __restrict__ bias, const float* __restrict__ bnp)
{
    extern __shared__ __align__(16) char smem[];
    const u32 smemBase = (u32)__cvta_generic_to_shared(smem);

    const int b  = blockIdx.z;
    const int mt = blockIdx.y;
    const int nt = blockIdx.x;
    const int tid  = threadIdx.x;
    const int lane = tid & 31;
    const int warp = tid >> 5;
    const int wm = warp & 3;       // 4 m-warps x 32 rows
    const int wn = warp >> 2;      // 2 n-warps x 128 cols

    const __half* Bg = Bsp + (size_t)b * (512 * 1024) + nt * 256;

    float acc[2][16][4];
    #pragma unroll
    for (int i = 0; i < 2; i++)
        #pragma unroll
        for (int j = 0; j < 16; j++)
            #pragma unroll
            for (int r = 0; r < 4; r++) acc[i][j][r] = 0.0f;

    auto load_stage = [&](int st, int k0) {
        u32 sb = smemBase + st * STG6;
        #pragma unroll
        for (int j = 0; j < 8; j++) {                  // A: 2048 x 16B
            int idx = j * 256 + tid;
            int s = idx >> 10, rem = idx & 1023;
            int m = rem >> 3, ch = rem & 7;
            cpa16(sb + s * ASTG6 + m * 144 + ch * 16,
                  W + ((size_t)(s * M + mt * 128 + m)) * 512 + k0 + ch * 8);
        }
        #pragma unroll
        for (int j = 0; j < 8; j++) {                  // B: 2048 x 16B
            int idx = j * 256 + tid;
            int br = idx >> 5, bc = idx & 31;
            cpa16(sb + A2SZ6 + br * 512 + ((bc ^ (br & 7)) << 4),
                  Bg + (size_t)(k0 + br) * 1024 + bc * 8);
        }
        cpa_commit();
    };

    load_stage(0, 0);

    for (int kt = 0; kt < 8; kt++) {
        if (kt + 1 < 8) {
            load_stage((kt + 1) & 1, (kt + 1) * 64);
            asm volatile("cp.async.wait_group 1;\n");
        } else {
            asm volatile("cp.async.wait_group 0;\n");
        }
        __syncthreads();

        const u32 aB = smemBase + (kt & 1) * STG6;
        const u32 bB = aB + A2SZ6;

        #pragma unroll
        for (int k16 = 0; k16 < 4; k16++) {
            u32 bfr[8][4];
            #pragma unroll
            for (int ni = 0; ni < 8; ni++) {
                int row = k16 * 16 + (lane & 15);
                int col = wn * 128 + ni * 16 + ((lane >> 4) << 3);
                int c = col >> 3;
                ldsm4t(bfr[ni], bB + row * 512 + ((c ^ (row & 7)) << 4));
            }
            // split 0 (weights h1, spikes at 1.0)
            {
                u32 afr[2][4];
                #pragma unroll
                for (int mi = 0; mi < 2; mi++) {
                    int row = wm * 32 + mi * 16 + (lane & 15);
                    ldsm4(afr[mi], aB + row * 144 + k16 * 32
                                   + ((lane >> 4) << 4));
                }
                #pragma unroll
                for (int mi = 0; mi < 2; mi++)
                    #pragma unroll
                    for (int j = 0; j < 16; j++)
                        mma_f16(acc[mi][j], afr[mi],
                                bfr[j >> 1][(j & 1) * 2],
                                bfr[j >> 1][(j & 1) * 2 + 1]);
            }
            // derive split-2 B fragments in-place: 1.0 -> 2^-12, 0 -> 0
            #pragma unroll
            for (int ni = 0; ni < 8; ni++)
                #pragma unroll
                for (int r = 0; r < 4; r++)
                    bfr[ni][r] &= 0x0C000C00u;
            // split 1 (weights f2 = fp16(r1*4096), spikes at 2^-12)
            {
                u32 afr[2][4];
                #pragma unroll
                for (int mi = 0; mi < 2; mi++) {
                    int row = wm * 32 + mi * 16 + (lane & 15);
                    ldsm4(afr[mi], aB + ASTG6 + row * 144 + k16 * 32
                                   + ((lane >> 4) << 4));
                }
                #pragma unroll
                for (int mi = 0; mi < 2; mi++)
                    #pragma unroll
                    for (int j = 0; j < 16; j++)
                        mma_f16(acc[mi][j], afr[mi],
                                bfr[j >> 1][(j & 1) * 2],
                                bfr[j >> 1][(j & 1) * 2 + 1]);
            }
        }
        __syncthreads();
    }

    // epilogue
    #pragma unroll
    for (int mi = 0; mi < 2; mi++) {
        #pragma unroll
        for (int r = 0; r < 2; r++) {
            int grow = mt * 128 + wm * 32 + mi * 16 + (lane >> 2) + r * 8;
            float* crow = C + (size_t)b * M * 1024 + (size_t)grow * 1024
                          + nt * 256 + wn * 128 + (lane & 3) * 2;
            float inv = 1.0f, mu = 0.0f, be = 0.0f, bi = 0.0f;
            if (EPI) {
                float g  = bnp[grow];
                be = bnp[512 + grow];
                mu = bnp[1024 + grow];
                float va = bnp[1536 + grow];
                inv = g * rsqrtf(va + 1e-5f);
                bi = bias[grow];
            }
            #pragma unroll
            for (int j = 0; j < 16; j++) {
                float v0 = acc[mi][j][r * 2];
                float v1 = acc[mi][j][r * 2 + 1];
                if (EPI) {
                    v0 = (v0 + bi - mu) * inv + be;
                    v1 = (v1 + bi - mu) * inv + be;
                }
                *(float2*)(crow + j * 8) = make_float2(v0, v1);
            }
        }
    }
}

// ---------------------------------------------------------------------------
// LIF (K1/K5): time-chunked, single fp16 spike output (0x3C00 = 1.0).
// ---------------------------------------------------------------------------
__global__ __launch_bounds__(32) void lif3h_kernel(
    const float* __restrict__ in, const float* __restrict__ bnp,
    __half* __restrict__ out, float vth)
{
    __shared__ float buf[32][33];
    const int lane = threadIdx.x;
    const int r0   = blockIdx.x * 32;
    const int row  = r0 + lane;
    const int ch   = blockIdx.y;

    float inv = 1.0f, mu = 0.0f, be = 0.0f;
    if (bnp) {
        int c = row & (CC - 1);
        inv = bnp[c] * (1.0f / sqrtf(bnp[3 * CC + c] + 1e-5f));
        be  = bnp[CC + c];
        mu  = bnp[2 * CC + c];
    }

    const int wt     = (ch == 0) ? 0 : (LWM / 32);
    const int ntiles = (LCH / 32) + wt;
    const int start  = ch * LCH - wt * 32;

    const float* src = in + (size_t)r0 * NN;
    __half* dst = out + (size_t)row * NN;

    float4 nxt[8];
    #pragma unroll
    for (int i = 0; i < 8; i++) {
        int f = lane + 32 * i;
        nxt[i] = *(const float4*)(src + (size_t)(f >> 3) * NN + start + (f & 7) * 4);
    }

    float v = 0.0f;
    for (int t = 0; t < ntiles; t++) {
        #pragma unroll
        for (int i = 0; i < 8; i++) {
            int f = lane + 32 * i;
            int r = f >> 3, c0 = (f & 7) * 4;
            buf[r][c0 + 0] = nxt[i].x;
            buf[r][c0 + 1] = nxt[i].y;
            buf[r][c0 + 2] = nxt[i].z;
            buf[r][c0 + 3] = nxt[i].w;
        }
        __syncwarp();
        if (t + 1 < ntiles) {
            #pragma unroll
            for (int i = 0; i < 8; i++) {
                int f = lane + 32 * i;
                nxt[i] = *(const float4*)(src + (size_t)(f >> 3) * NN
                                          + start + (t + 1) * 32 + (f & 7) * 4);
            }
        }
        u32 pk[16];
        #pragma unroll
        for (int kk = 0; kk < 32; kk++) {
            float x  = buf[lane][kk];
            float xb = (x - mu) * inv + be;
            v = v + (xb - v) * 0.5f;
            bool sp = (v >= vth);
            v = sp ? 0.0f : v;
            u32 sb = sp ? 0x3C00u : 0u;                // fp16 1.0
            if (kk & 1) pk[kk >> 1] |= sb << 16;
            else        pk[kk >> 1]  = sb;
        }
        __syncwarp();
        if (t >= wt) {
            int col = start + t * 32;
            #pragma unroll
            for (int j = 0; j < 4; j++) {
                uint4 q = make_uint4(pk[j*4], pk[j*4+1], pk[j*4+2], pk[j*4+3]);
                *(uint4*)(dst + col + j * 8) = q;
            }
        }
    }
}

// ---------------------------------------------------------------------------
// LIF (K3): time-chunked BN+LIF on QKV output; q -> bf16, k/v -> bitpacked.
// ---------------------------------------------------------------------------
__global__ __launch_bounds__(32) void lif_qkv3_kernel(
    const float* __restrict__ bnq, const float* __restrict__ bnk,
    const float* __restrict__ bnv)
{
    __shared__ float buf[32][33];
    const int lane = threadIdx.x;
    const int r0g  = blockIdx.x * 32;
    const int ch   = blockIdx.y;
    const int b    = r0g / CQKV;
    const int o    = r0g % CQKV;
    const int br   = o >> 9;
    const int c    = (o & 511) + lane;

    const float* bnp = (br == 0) ? bnq : (br == 1) ? bnk : bnv;
    float inv = bnp[c] * (1.0f / sqrtf(bnp[3 * CC + c] + 1e-5f));
    float be  = bnp[CC + c];
    float mu  = bnp[2 * CC + c];

    const int wt     = (ch == 0) ? 0 : (LWM / 32);
    const int ntiles = (LCH / 32) + wt;
    const int start  = ch * LCH - wt * 32;

    const float* src = g_z + (size_t)r0g * NN;
    __nv_bfloat16* qdst = g_sqh + ((size_t)b * CC + c) * NN;
    u64* bdst = ((br == 1) ? g_kb : g_vb) + ((size_t)b * CC + c) * 16;

    float4 nxt[8];
    #pragma unroll
    for (int i = 0; i < 8; i++) {
        int f = lane + 32 * i;
        nxt[i] = *(const float4*)(src + (size_t)(f >> 3) * NN + start + (f & 7) * 4);
    }

    float v = 0.0f;
    u32 prevbits = 0;
    for (int t = 0; t < ntiles; t++) {
        #pragma unroll
        for (int i = 0; i < 8; i++) {
            int f = lane + 32 * i;
            int r = f >> 3, cc = (f & 7) * 4;
            buf[r][cc + 0] = nxt[i].x;
            buf[r][cc + 1] = nxt[i].y;
            buf[r][cc + 2] = nxt[i].z;
            buf[r][cc + 3] = nxt[i].w;
        }
        __syncwarp();
        if (t + 1 < ntiles) {
            #pragma unroll
            for (int i = 0; i < 8; i++) {
                int f = lane + 32 * i;
                nxt[i] = *(const float4*)(src + (size_t)(f >> 3) * NN
                                          + start + (t + 1) * 32 + (f & 7) * 4);
            }
        }
        u32 pk[16];
        u32 tb = 0;
        #pragma unroll
        for (int kk = 0; kk < 32; kk++) {
            float x  = buf[lane][kk];
            float xb = (x - mu) * inv + be;
            v = v + (xb - v) * 0.5f;
            bool sp = (v >= 1.0f);
            v = sp ? 0.0f : v;
            if (br == 0) {
                u32 sbv = sp ? 0x3F80u : 0u;
                if (kk & 1) pk[kk >> 1] |= sbv << 16;
                else        pk[kk >> 1]  = sbv;
            } else {
                tb |= (sp ? 1u : 0u) << kk;
            }
        }
        __syncwarp();
        if (t >= wt) {
            int et  = t - wt;
            int col = ch * LCH + et * 32;
            if (br == 0) {
                #pragma unroll
                for (int j = 0; j < 4; j++) {
                    uint4 q = make_uint4(pk[j*4], pk[j*4+1], pk[j*4+2], pk[j*4+3]);
                    *(uint4*)(qdst + col + j * 8) = q;
                }
            } else {
                if (et & 1) bdst[ch * 2 + (et >> 1)] = ((u64)tb << 32) | (u64)prevbits;
                else        prevbits = tb;
            }
        }
    }
}

// ---------------------------------------------------------------------------
// attn: y = q @ (k^T v) * 0.25 per (b,h); d-split x2, n-split x8.
// ---------------------------------------------------------------------------
__global__ __launch_bounds__(128) void attn3_kernel()
{
    __shared__ u64 kbs[64][16];
    __shared__ u64 vbs[32][16];
    __shared__ __align__(16) float Gs[64][32];

    const int nc = blockIdx.x;
    const int h  = blockIdx.y >> 1;
    const int dh = blockIdx.y & 1;
    const int b  = blockIdx.z;
    const int tid = threadIdx.x;
    const size_t base_c = (size_t)b * CC + h * DD;

    for (int i = tid; i < 64 * 16; i += 128) {
        int d = i >> 4, j = i & 15;
        kbs[d][j] = g_kb[(base_c + d) * 16 + j];
    }
    for (int i = tid; i < 32 * 16; i += 128) {
        int d = i >> 4, j = i & 15;
        vbs[d][j] = g_vb[(base_c + dh * 32 + d) * 16 + j];
    }
    __syncthreads();

    for (int e = tid; e < 64 * 32; e += 128) {
        int dp = e >> 5, dd = e & 31;
        int gsum = 0;
        #pragma unroll
        for (int j = 0; j < 16; j++)
            gsum += __popcll(kbs[dp][j] & vbs[dd][j]);
        Gs[dp][dd] = (float)gsum;
    }
    __syncthreads();

    const int n = nc * 128 + tid;
    const __nv_bfloat16* qb = g_sqh + base_c * NN + n;

    float acc[32];
    #pragma unroll
    for (int d = 0; d < 32; d++) acc[d] = 0.0f;

    #pragma unroll 4
    for (int dp = 0; dp < 64; dp++) {
        float qv = __bfloat162float(qb[(size_t)dp * NN]);
        const float4* gr = (const float4*)&Gs[dp][0];
        #pragma unroll
        for (int j = 0; j < 8; j++) {
            float4 g4 = gr[j];
            acc[j * 4 + 0] += qv * g4.x;
            acc[j * 4 + 1] += qv * g4.y;
            acc[j * 4 + 2] += qv * g4.z;
            acc[j * 4 + 3] += qv * g4.w;
        }
    }
    #pragma unroll
    for (int d = 0; d < 32; d++)
        g_y[(base_c + dh * 32 + d) * NN + n] = acc[d] * 0.25f;
}

// ---------------------------------------------------------------------------
// Launch
// ---------------------------------------------------------------------------
extern "C" void kernel_launch(void* const* d_in, const int* in_sizes, int n_in,
                              void* d_out, int out_size)
{
    const float* x       = (const float*)d_in[0];
    const float* bn_pre  = (const float*)d_in[1];
    const float* w_q     = (const float*)d_in[2];
    const float* bn_q    = (const float*)d_in[3];
    const float* w_k     = (const float*)d_in[4];
    const float* bn_k    = (const float*)d_in[5];
    const float* w_v     = (const float*)d_in[6];
    const float* bn_v    = (const float*)d_in[7];
    const float* w_proj  = (const float*)d_in[8];
    const float* b_proj  = (const float*)d_in[9];
    const float* bn_proj = (const float*)d_in[10];
    float* out = (float*)d_out;

    __half* xq_ptr; cudaGetSymbolAddress((void**)&xq_ptr, g_xq);
    __half* sy_ptr; cudaGetSymbolAddress((void**)&sy_ptr, g_sy);
    __half* hA_ptr; cudaGetSymbolAddress((void**)&hA_ptr, g_hA);
    __half* hP_ptr; cudaGetSymbolAddress((void**)&hP_ptr, g_hP);
    float* z_ptr;  cudaGetSymbolAddress((void**)&z_ptr, g_z);
    float* y_ptr;  cudaGetSymbolAddress((void**)&y_ptr, g_y);

    cudaFuncSetAttribute(gemm6_kernel<false>,
                         cudaFuncAttributeMaxDynamicSharedMemorySize, GSM6);
    cudaFuncSetAttribute(gemm6_kernel<true>,
                         cudaFuncAttributeMaxDynamicSharedMemorySize, GSM6);

    // P0: 2-way fp16 weight splits, [s][m][k]
    split_kernel<<<(CQKV * CC) / 256, 256>>>(w_q, w_k, w_v, w_proj);

    // K1: pre BN + LIF -> xq spikes (fp16), time-chunked
    lif3h_kernel<<<dim3((BB * CC) / 32, NN / LCH), 32>>>(x, bn_pre, xq_ptr, 1.0f);

    // K2: fused QKV GEMM (fp16 HMMA, 2-split, single-B + register AND)
    gemm6_kernel<false><<<dim3(NN / 256, CQKV / 128, BB), 256, GSM6>>>(
        hA_ptr, xq_ptr, z_ptr, CQKV, nullptr, nullptr);

    // K3: per-branch BN + LIF (time-chunked); q -> bf16, k/v -> bitpacked
    lif_qkv3_kernel<<<dim3((BB * CQKV) / 32, NN / LCH), 32>>>(bn_q, bn_k, bn_v);

    // K4: linear attention via G = k^T v (popcount), y = q G * 0.25
    attn3_kernel<<<dim3(8, 16, 8), 128>>>();

    // K5: attn LIF (threshold 0.5) -> sy spikes (fp16), time-chunked
    lif3h_kernel<<<dim3((BB * CC) / 32, NN / LCH), 32>>>(
        y_ptr, nullptr, sy_ptr, 0.5f);

    // K6: projection GEMM + bias + bn_proj fused epilogue -> out
    gemm6_kernel<true><<<dim3(NN / 256, CC / 128, BB), 256, GSM6>>>(
        hP_ptr, sy_ptr, out, CC, b_proj, bn_proj);
}